// round 10
// baseline (speedup 1.0000x reference)
#include <cuda_runtime.h>

// SimpleLSTM: B=4096, T=256, I=16, H=32, O=1 (fp32)
// R10: ALL weights in smem (conflict-free float4/lane), BPW=2, ~100 regs ->
// 16 warps/SM (4/SMSP) instead of 8. FFMA2 pipe becomes the binding resource.
// Warp = 2 batches; lane j owns hidden unit j. Gate order [i,f,g,o], sigmoid
// folded as fma(tanh(0.5x),0.5,0.5) with 0.5 pre-scaled into weights/bias.
// x staged via cp.async double-buffer; h broadcast via smem double-buffer.

#define BB 4096
#define TT 256
#define II 16
#define HH 32
#define WARPS_PER_BLK 4
#define THREADS (WARPS_PER_BLK * 32)
#define BPW 2   // batches per warp

typedef unsigned long long ull;

__device__ __forceinline__ void ffma2(ull& acc, ull a, ull b) {
    asm("fma.rn.f32x2 %0, %1, %2, %0;" : "+l"(acc) : "l"(a), "l"(b));
}
__device__ __forceinline__ float hadd2(ull v) {
    float lo, hi;
    asm("mov.b64 {%0, %1}, %2;" : "=f"(lo), "=f"(hi) : "l"(v));
    return lo + hi;
}
__device__ __forceinline__ ull pack2(float lo, float hi) {
    ull r;
    asm("mov.b64 %0, {%1, %2};" : "=l"(r) : "f"(lo), "f"(hi));
    return r;
}
__device__ __forceinline__ float tanh_a(float v) {
    float r;
    asm("tanh.approx.f32 %0, %1;" : "=f"(r) : "f"(v));   // MUFU.TANH
    return r;
}
__device__ __forceinline__ void cp_async16(void* smem_dst, const void* gsrc) {
    unsigned saddr = (unsigned)__cvta_generic_to_shared(smem_dst);
    asm volatile("cp.async.ca.shared.global [%0], [%1], 16;" :: "r"(saddr), "l"(gsrc));
}
__device__ __forceinline__ void cp_commit() {
    asm volatile("cp.async.commit_group;" ::: "memory");
}
__device__ __forceinline__ void cp_wait1() {
    asm volatile("cp.async.wait_group 1;" ::: "memory");
}

__global__ void __launch_bounds__(THREADS, 4)
lstm_smemw_kernel(const float* __restrict__ x,      // [B,T,I]
                  const float* __restrict__ W_ih,   // [4H,I]
                  const float* __restrict__ W_hh,   // [4H,H]
                  const float* __restrict__ b_ih,   // [4H]
                  const float* __restrict__ b_hh,   // [4H]
                  const float* __restrict__ W_fc,   // [1,H]
                  const float* __restrict__ b_fc,   // [1]
                  float* __restrict__ out)          // [B,1]
{
    // whhA[p][j] = {0.5*Wi[j][2p..+1], 0.5*Wf[j][2p..+1]}  (p = k-pair 0..15)
    // whhB[p][j] = {Wg[j][2p..+1],     0.5*Wo[j][2p..+1]}
    __shared__ float4 whhA[HH / 2][HH];
    __shared__ float4 whhB[HH / 2][HH];
    // wihA[i2][j] = {0.5*Wi pair, 0.5*Wf pair}; wihB = {Wg pair, 0.5*Wo pair}
    __shared__ float4 wihA[II / 2][HH];
    __shared__ float4 wihB[II / 2][HH];
    __shared__ float  h_s[WARPS_PER_BLK][2][BPW][HH];   // h broadcast, dbl-buffer
    __shared__ float  xs[WARPS_PER_BLK][2][BPW][II];    // x staging, dbl-buffer

    const int tid = threadIdx.x;
    const int wid = tid >> 5;
    const int j   = tid & 31;
    const int b0  = (blockIdx.x * WARPS_PER_BLK + wid) * BPW;

    // ---- stage weights (once per block), gate-scaled ----
    for (int idx = tid; idx < (HH / 2) * HH; idx += THREADS) {
        int p = idx >> 5, jj = idx & 31;
        whhA[p][jj] = make_float4(0.5f * W_hh[(0 * HH + jj) * HH + 2 * p],
                                  0.5f * W_hh[(0 * HH + jj) * HH + 2 * p + 1],
                                  0.5f * W_hh[(1 * HH + jj) * HH + 2 * p],
                                  0.5f * W_hh[(1 * HH + jj) * HH + 2 * p + 1]);
        whhB[p][jj] = make_float4(W_hh[(2 * HH + jj) * HH + 2 * p],
                                  W_hh[(2 * HH + jj) * HH + 2 * p + 1],
                                  0.5f * W_hh[(3 * HH + jj) * HH + 2 * p],
                                  0.5f * W_hh[(3 * HH + jj) * HH + 2 * p + 1]);
    }
    for (int idx = tid; idx < (II / 2) * HH; idx += THREADS) {
        int i2 = idx >> 5, jj = idx & 31;
        wihA[i2][jj] = make_float4(0.5f * W_ih[(0 * HH + jj) * II + 2 * i2],
                                   0.5f * W_ih[(0 * HH + jj) * II + 2 * i2 + 1],
                                   0.5f * W_ih[(1 * HH + jj) * II + 2 * i2],
                                   0.5f * W_ih[(1 * HH + jj) * II + 2 * i2 + 1]);
        wihB[i2][jj] = make_float4(W_ih[(2 * HH + jj) * II + 2 * i2],
                                   W_ih[(2 * HH + jj) * II + 2 * i2 + 1],
                                   0.5f * W_ih[(3 * HH + jj) * II + 2 * i2],
                                   0.5f * W_ih[(3 * HH + jj) * II + 2 * i2 + 1]);
    }
    __syncthreads();

    // biases packed as (bias, 0): carried by accumulator init
    ull biasp[4];
    biasp[0] = pack2(0.5f * (b_ih[0 * HH + j] + b_hh[0 * HH + j]), 0.0f);
    biasp[1] = pack2(0.5f * (b_ih[1 * HH + j] + b_hh[1 * HH + j]), 0.0f);
    biasp[2] = pack2(        b_ih[2 * HH + j] + b_hh[2 * HH + j],  0.0f);
    biasp[3] = pack2(0.5f * (b_ih[3 * HH + j] + b_hh[3 * HH + j]), 0.0f);

    const ulonglong2* wA  = reinterpret_cast<const ulonglong2*>(&wihA[0][j]);
    const ulonglong2* wB  = reinterpret_cast<const ulonglong2*>(&wihB[0][j]);
    const ulonglong2* wRA = reinterpret_cast<const ulonglong2*>(&whhA[0][j]);
    const ulonglong2* wRB = reinterpret_cast<const ulonglong2*>(&whhB[0][j]);

    // cp.async: lanes 0..7 -> batch j>>2 (0..1), 16B chunk j&3
    const int cb = j >> 2, cc = j & 3;
    const float* gsrc = x + (long)(b0 + cb) * TT * II + cc * 4;

    float h[BPW] = {0.f, 0.f};
    float c[BPW] = {0.f, 0.f};

    // prefetch x(t=0) into buffer 0
    if (j < 8) cp_async16(&xs[wid][0][cb][cc * 4], gsrc);
    cp_commit();

    #pragma unroll 1
    for (int t = 0; t < TT; t++) {
        const int bufx = t & 1;

        // broadcast h (state after step t-1)
        h_s[wid][bufx][0][j] = h[0];
        h_s[wid][bufx][1][j] = h[1];

        // prefetch x(t+1) into other buffer (always commit: constant depth)
        const long tn = (t + 1 < TT) ? t + 1 : t;
        if (j < 8) cp_async16(&xs[wid][bufx ^ 1][cb][cc * 4], gsrc + tn * II);
        cp_commit();
        cp_wait1();          // current step's x resident
        __syncwarp();        // h + x visible warp-wide

        ull ai[BPW], af[BPW], ag[BPW], ao[BPW];
        #pragma unroll
        for (int bb = 0; bb < BPW; bb++) {
            ai[bb] = biasp[0]; af[bb] = biasp[1];
            ag[bb] = biasp[2]; ao[bb] = biasp[3];
        }

        // ---- input projection (weights from smem, shared by 2 batches) ----
        const ulonglong2* xs0 = reinterpret_cast<const ulonglong2*>(&xs[wid][bufx][0][0]);
        const ulonglong2* xs1 = reinterpret_cast<const ulonglong2*>(&xs[wid][bufx][1][0]);
        #pragma unroll
        for (int q = 0; q < 4; q++) {
            ulonglong2 x0 = xs0[q];                  // 2 pairs, batch 0
            ulonglong2 x1 = xs1[q];                  // 2 pairs, batch 1
            ulonglong2 a0 = wA[(2 * q) * 32], a1 = wA[(2 * q + 1) * 32];
            ulonglong2 g0 = wB[(2 * q) * 32], g1 = wB[(2 * q + 1) * 32];
            ffma2(ai[0], a0.x, x0.x); ffma2(ai[0], a1.x, x0.y);
            ffma2(ai[1], a0.x, x1.x); ffma2(ai[1], a1.x, x1.y);
            ffma2(af[0], a0.y, x0.x); ffma2(af[0], a1.y, x0.y);
            ffma2(af[1], a0.y, x1.x); ffma2(af[1], a1.y, x1.y);
            ffma2(ag[0], g0.x, x0.x); ffma2(ag[0], g1.x, x0.y);
            ffma2(ag[1], g0.x, x1.x); ffma2(ag[1], g1.x, x1.y);
            ffma2(ao[0], g0.y, x0.x); ffma2(ao[0], g1.y, x0.y);
            ffma2(ao[1], g0.y, x1.x); ffma2(ao[1], g1.y, x1.y);
        }

        // ---- recurrent matvec (weights from smem, shared by 2 batches) ----
        const ulonglong2* hb0 = reinterpret_cast<const ulonglong2*>(&h_s[wid][bufx][0][0]);
        const ulonglong2* hb1 = reinterpret_cast<const ulonglong2*>(&h_s[wid][bufx][1][0]);
        #pragma unroll
        for (int kk = 0; kk < 8; kk++) {
            ulonglong2 hq0 = hb0[kk];                // h[4kk..4kk+3], batch 0
            ulonglong2 hq1 = hb1[kk];
            ulonglong2 wa0 = wRA[(2 * kk) * 32];     // p=2kk:   (wi, wf) pairs
            ulonglong2 wa1 = wRA[(2 * kk + 1) * 32]; // p=2kk+1
            ulonglong2 wb0 = wRB[(2 * kk) * 32];     //          (wg, wo) pairs
            ulonglong2 wb1 = wRB[(2 * kk + 1) * 32];
            ffma2(ai[0], wa0.x, hq0.x); ffma2(ai[0], wa1.x, hq0.y);
            ffma2(ai[1], wa0.x, hq1.x); ffma2(ai[1], wa1.x, hq1.y);
            ffma2(af[0], wa0.y, hq0.x); ffma2(af[0], wa1.y, hq0.y);
            ffma2(af[1], wa0.y, hq1.x); ffma2(af[1], wa1.y, hq1.y);
            ffma2(ag[0], wb0.x, hq0.x); ffma2(ag[0], wb1.x, hq0.y);
            ffma2(ag[1], wb0.x, hq1.x); ffma2(ag[1], wb1.x, hq1.y);
            ffma2(ao[0], wb0.y, hq0.x); ffma2(ao[0], wb1.y, hq0.y);
            ffma2(ao[1], wb0.y, hq1.x); ffma2(ao[1], wb1.y, hq1.y);
        }

        // ---- activations (MUFU.TANH; i,f,o pre-scaled by 0.5) ----
        #pragma unroll
        for (int bb = 0; bb < BPW; bb++) {
            float gi = fmaf(tanh_a(hadd2(ai[bb])), 0.5f, 0.5f);
            float gf = fmaf(tanh_a(hadd2(af[bb])), 0.5f, 0.5f);
            float gg = tanh_a(hadd2(ag[bb]));
            float go = fmaf(tanh_a(hadd2(ao[bb])), 0.5f, 0.5f);
            c[bb] = fmaf(gf, c[bb], gi * gg);
            h[bb] = go * tanh_a(c[bb]);
        }
    }

    // ---- final FC (O=1): 2 warp reductions ----
    float wf = W_fc[j];
    float v0 = h[0] * wf, v1 = h[1] * wf;
    #pragma unroll
    for (int off = 16; off; off >>= 1) {
        v0 += __shfl_xor_sync(0xffffffffu, v0, off);
        v1 += __shfl_xor_sync(0xffffffffu, v1, off);
    }
    if (j == 0) {
        float bf = b_fc[0];
        out[b0 + 0] = v0 + bf;
        out[b0 + 1] = v1 + bf;
    }
}

extern "C" void kernel_launch(void* const* d_in, const int* in_sizes, int n_in,
                              void* d_out, int out_size) {
    (void)in_sizes; (void)n_in; (void)out_size;
    const float* x    = (const float*)d_in[0];
    const float* W_ih = (const float*)d_in[1];
    const float* W_hh = (const float*)d_in[2];
    const float* b_ih = (const float*)d_in[3];
    const float* b_hh = (const float*)d_in[4];
    const float* W_fc = (const float*)d_in[5];
    const float* b_fc = (const float*)d_in[6];
    float* out = (float*)d_out;

    dim3 grid(BB / (BPW * WARPS_PER_BLK));   // 512 blocks, 3-4 per SM
    dim3 block(THREADS);
    lstm_smemw_kernel<<<grid, block>>>(x, W_ih, W_hh, b_ih, b_hh, W_fc, b_fc, out);
}

// round 11
// speedup vs baseline: 1.5670x; 1.5670x over previous
#include <cuda_runtime.h>

// SimpleLSTM: B=4096, T=256, I=16, H=32, O=1 (fp32)
// R11 = R5 design (warp owns batches, lane j owns hidden unit j, W_hh f32x2
// pairs in registers, W_ih smem, h broadcast dbl-buffer, x cp.async dbl-buffer)
// + full-chip balance: 148 CTAs x 8 warps; 544 warps run 4 batches, 640 run 3
// (templated step loop so NB=3 warps really issue fewer FFMA2).
// Max per-SMSP load drops 8 -> 7 batches.

#define BB 4096
#define TT 256
#define II 16
#define HH 32
#define WARPS_PER_BLK 8
#define THREADS (WARPS_PER_BLK * 32)
#define NCTA 148
#define NWARP (NCTA * WARPS_PER_BLK)          // 1184
#define N4 (BB - 3 * NWARP)                   // 544 warps with 4 batches
// remaining 640 warps carry 3 batches: 544*4 + 640*3 = 4096

typedef unsigned long long ull;

__device__ __forceinline__ void ffma2(ull& acc, ull a, ull b) {
    asm("fma.rn.f32x2 %0, %1, %2, %0;" : "+l"(acc) : "l"(a), "l"(b));
}
__device__ __forceinline__ float hadd2(ull v) {
    float lo, hi;
    asm("mov.b64 {%0, %1}, %2;" : "=f"(lo), "=f"(hi) : "l"(v));
    return lo + hi;
}
__device__ __forceinline__ ull pack2(float lo, float hi) {
    ull r;
    asm("mov.b64 %0, {%1, %2};" : "=l"(r) : "f"(lo), "f"(hi));
    return r;
}
__device__ __forceinline__ float tanh_a(float v) {
    float r;
    asm("tanh.approx.f32 %0, %1;" : "=f"(r) : "f"(v));   // MUFU.TANH
    return r;
}
__device__ __forceinline__ void cp_async16(void* smem_dst, const void* gsrc) {
    unsigned saddr = (unsigned)__cvta_generic_to_shared(smem_dst);
    asm volatile("cp.async.ca.shared.global [%0], [%1], 16;" :: "r"(saddr), "l"(gsrc));
}
__device__ __forceinline__ void cp_commit() {
    asm volatile("cp.async.commit_group;" ::: "memory");
}
__device__ __forceinline__ void cp_wait1() {
    asm volatile("cp.async.wait_group 1;" ::: "memory");
}

// ---- templated step loop: NB = batches this warp owns (3 or 4) ----
template <int NB>
__device__ __forceinline__ void lstm_run(
    const int j, const int b0,
    const float* __restrict__ x,
    const ulonglong2* wA, const ulonglong2* wB,   // &wih[ ][j], stride 32 f4
    const ull* biasp,                              // 4 packed (bias,0)
    const ull (&whh2)[4][HH / 2],                  // register weights (scaled)
    float (*h_sw)[4][HH],                          // [2][4][HH] this warp
    float (*xsw)[4][II],                           // [2][4][II]  this warp
    const float* __restrict__ W_fc,
    const float* __restrict__ b_fc,
    float* __restrict__ out)
{
    // cp.async lane map: lanes 0..4*NB-1 -> batch j>>2, 16B chunk j&3
    const int cb = j >> 2, cc = j & 3;
    const float* gsrc = x + (long)(b0 + cb) * TT * II + cc * 4;

    float h[NB], c[NB];
    #pragma unroll
    for (int bb = 0; bb < NB; bb++) { h[bb] = 0.f; c[bb] = 0.f; }

    if (j < 4 * NB) cp_async16(&xsw[0][cb][cc * 4], gsrc);
    cp_commit();

    #pragma unroll 1
    for (int t = 0; t < TT; t++) {
        const int bufx = t & 1;

        // broadcast h (state after step t-1)
        #pragma unroll
        for (int bb = 0; bb < NB; bb++)
            h_sw[bufx][bb][j] = h[bb];

        // prefetch x(t+1) into other buffer (constant group depth)
        const long tn = (t + 1 < TT) ? t + 1 : t;
        if (j < 4 * NB) cp_async16(&xsw[bufx ^ 1][cb][cc * 4], gsrc + tn * II);
        cp_commit();
        cp_wait1();          // current step's x resident
        __syncwarp();        // h + x visible warp-wide

        ull ai[NB], af[NB], ag[NB], ao[NB];
        #pragma unroll
        for (int bb = 0; bb < NB; bb++) {
            ai[bb] = biasp[0]; af[bb] = biasp[1];
            ag[bb] = biasp[2]; ao[bb] = biasp[3];
        }

        // ---- load x pairs (broadcast LDS.128) ----
        ull xp[NB][8];
        #pragma unroll
        for (int bb = 0; bb < NB; bb++) {
            const ulonglong2* xs2 = reinterpret_cast<const ulonglong2*>(&xsw[bufx][bb][0]);
            ulonglong2 q0 = xs2[0], q1 = xs2[1], q2 = xs2[2], q3 = xs2[3];
            xp[bb][0] = q0.x; xp[bb][1] = q0.y; xp[bb][2] = q1.x; xp[bb][3] = q1.y;
            xp[bb][4] = q2.x; xp[bb][5] = q2.y; xp[bb][6] = q3.x; xp[bb][7] = q3.y;
        }

        // ---- input projection: one smem weight read feeds NB batches ----
        #pragma unroll
        for (int i2 = 0; i2 < 8; i2++) {
            ulonglong2 a  = wA[i2 * 32];
            ulonglong2 w2 = wB[i2 * 32];
            #pragma unroll
            for (int bb = 0; bb < NB; bb++) {
                ffma2(ai[bb], a.x,  xp[bb][i2]);
                ffma2(af[bb], a.y,  xp[bb][i2]);
                ffma2(ag[bb], w2.x, xp[bb][i2]);
                ffma2(ao[bb], w2.y, xp[bb][i2]);
            }
        }

        // ---- recurrent matvec: register weights, 4*NB independent chains ----
        #pragma unroll
        for (int kk = 0; kk < 8; kk++) {
            ulonglong2 hq[NB];
            #pragma unroll
            for (int bb = 0; bb < NB; bb++)
                hq[bb] = reinterpret_cast<const ulonglong2*>(&h_sw[bufx][bb][0])[kk];
            #pragma unroll
            for (int bb = 0; bb < NB; bb++) {
                ffma2(ai[bb], whh2[0][2*kk], hq[bb].x); ffma2(ai[bb], whh2[0][2*kk+1], hq[bb].y);
                ffma2(af[bb], whh2[1][2*kk], hq[bb].x); ffma2(af[bb], whh2[1][2*kk+1], hq[bb].y);
                ffma2(ag[bb], whh2[2][2*kk], hq[bb].x); ffma2(ag[bb], whh2[2][2*kk+1], hq[bb].y);
                ffma2(ao[bb], whh2[3][2*kk], hq[bb].x); ffma2(ao[bb], whh2[3][2*kk+1], hq[bb].y);
            }
        }

        // ---- activations (MUFU.TANH; i,f,o pre-scaled by 0.5) ----
        #pragma unroll
        for (int bb = 0; bb < NB; bb++) {
            float gi = fmaf(tanh_a(hadd2(ai[bb])), 0.5f, 0.5f);
            float gf = fmaf(tanh_a(hadd2(af[bb])), 0.5f, 0.5f);
            float gg = tanh_a(hadd2(ag[bb]));
            float go = fmaf(tanh_a(hadd2(ao[bb])), 0.5f, 0.5f);
            c[bb] = fmaf(gf, c[bb], gi * gg);
            h[bb] = go * tanh_a(c[bb]);
        }
    }

    // ---- final FC (O=1): NB warp reductions ----
    float wf = W_fc[j];
    float v[NB];
    #pragma unroll
    for (int bb = 0; bb < NB; bb++) v[bb] = h[bb] * wf;
    #pragma unroll
    for (int off = 16; off; off >>= 1) {
        #pragma unroll
        for (int bb = 0; bb < NB; bb++)
            v[bb] += __shfl_xor_sync(0xffffffffu, v[bb], off);
    }
    if (j == 0) {
        float bf = b_fc[0];
        #pragma unroll
        for (int bb = 0; bb < NB; bb++)
            out[b0 + bb] = v[bb] + bf;
    }
}

__global__ void __launch_bounds__(THREADS, 1)
lstm_bal_kernel(const float* __restrict__ x,      // [B,T,I]
                const float* __restrict__ W_ih,   // [4H,I]
                const float* __restrict__ W_hh,   // [4H,H]
                const float* __restrict__ b_ih,   // [4H]
                const float* __restrict__ b_hh,   // [4H]
                const float* __restrict__ W_fc,   // [1,H]
                const float* __restrict__ b_fc,   // [1]
                float* __restrict__ out)          // [B,1]
{
    // wihA[i2][j] = {0.5*Wi pair, 0.5*Wf pair}; wihB[i2][j] = {Wg pair, 0.5*Wo pair}
    __shared__ float4 wihA[II / 2][HH];
    __shared__ float4 wihB[II / 2][HH];
    __shared__ float  h_s[WARPS_PER_BLK][2][4][HH];
    __shared__ float  xs[WARPS_PER_BLK][2][4][II];

    const int tid = threadIdx.x;
    const int wid = tid >> 5;
    const int j   = tid & 31;

    // ---- stage W_ih (once per block), gate-scaled ----
    for (int idx = tid; idx < (II / 2) * HH; idx += THREADS) {
        int i2 = idx >> 5, jj = idx & 31;
        wihA[i2][jj] = make_float4(0.5f * W_ih[(0 * HH + jj) * II + 2 * i2],
                                   0.5f * W_ih[(0 * HH + jj) * II + 2 * i2 + 1],
                                   0.5f * W_ih[(1 * HH + jj) * II + 2 * i2],
                                   0.5f * W_ih[(1 * HH + jj) * II + 2 * i2 + 1]);
        wihB[i2][jj] = make_float4(W_ih[(2 * HH + jj) * II + 2 * i2],
                                   W_ih[(2 * HH + jj) * II + 2 * i2 + 1],
                                   0.5f * W_ih[(3 * HH + jj) * II + 2 * i2],
                                   0.5f * W_ih[(3 * HH + jj) * II + 2 * i2 + 1]);
    }
    __syncthreads();

    // ---- W_hh rows (4 gates) as packed pairs, gate-scaled (128 regs) ----
    const float gsc[4] = {0.5f, 0.5f, 1.0f, 0.5f};
    ull whh2[4][HH / 2];
    #pragma unroll
    for (int g = 0; g < 4; g++) {
        const float* wrow = W_hh + (g * HH + j) * HH;
        #pragma unroll
        for (int k2 = 0; k2 < HH / 2; k2++)
            whh2[g][k2] = pack2(gsc[g] * wrow[2 * k2], gsc[g] * wrow[2 * k2 + 1]);
    }

    ull biasp[4];
    #pragma unroll
    for (int g = 0; g < 4; g++)
        biasp[g] = pack2(gsc[g] * (b_ih[g * HH + j] + b_hh[g * HH + j]), 0.0f);

    const ulonglong2* wA = reinterpret_cast<const ulonglong2*>(&wihA[0][j]);
    const ulonglong2* wB = reinterpret_cast<const ulonglong2*>(&wihB[0][j]);

    // ---- warp -> batch range: first N4 warps take 4, rest take 3 ----
    const int gw = blockIdx.x * WARPS_PER_BLK + wid;
    if (gw < N4) {
        lstm_run<4>(j, gw * 4, x, wA, wB, biasp, whh2,
                    h_s[wid], xs[wid], W_fc, b_fc, out);
    } else {
        lstm_run<3>(j, N4 * 4 + (gw - N4) * 3, x, wA, wB, biasp, whh2,
                    h_s[wid], xs[wid], W_fc, b_fc, out);
    }
}

extern "C" void kernel_launch(void* const* d_in, const int* in_sizes, int n_in,
                              void* d_out, int out_size) {
    (void)in_sizes; (void)n_in; (void)out_size;
    const float* x    = (const float*)d_in[0];
    const float* W_ih = (const float*)d_in[1];
    const float* W_hh = (const float*)d_in[2];
    const float* b_ih = (const float*)d_in[3];
    const float* b_hh = (const float*)d_in[4];
    const float* W_fc = (const float*)d_in[5];
    const float* b_fc = (const float*)d_in[6];
    float* out = (float*)d_out;

    dim3 grid(NCTA);      // 148 CTAs, 1 per SM, single wave
    dim3 block(THREADS);
    lstm_bal_kernel<<<grid, block>>>(x, W_ih, W_hh, b_ih, b_hh, W_fc, b_fc, out);
}

// round 12
// speedup vs baseline: 1.7738x; 1.1320x over previous
#include <cuda_runtime.h>

// SimpleLSTM: B=4096, T=256, I=16, H=32, O=1 (fp32)
// R12 = R5 body + SMSP-level load balance:
//   148 CTAs x 8 warps. In 136 CTAs, warps 0-3 carry 4 batches and warps 4-7
//   carry 3 (SMSP pairs (w, w+4) -> 7 batches each, was 8). Remaining 12 CTAs
//   all-NB=3. Totals: 136*28 + 12*24 = 4096.
// Warp owns its batches; lane j owns hidden unit j. W_hh f32x2 pairs in regs,
// W_ih smem (16B/lane conflict-free), h broadcast smem dbl-buffer, x via
// cp.async dbl-buffer, MUFU.TANH activations with 0.5 folded into weights.

#define BB 4096
#define TT 256
#define II 16
#define HH 32
#define WARPS_PER_BLK 8
#define THREADS (WARPS_PER_BLK * 32)
#define NCTA 148
#define NHEAVY 136   // CTAs with 4+3 split; rest all-3

typedef unsigned long long ull;

__device__ __forceinline__ void ffma2(ull& acc, ull a, ull b) {
    asm("fma.rn.f32x2 %0, %1, %2, %0;" : "+l"(acc) : "l"(a), "l"(b));
}
__device__ __forceinline__ float hadd2(ull v) {
    float lo, hi;
    asm("mov.b64 {%0, %1}, %2;" : "=f"(lo), "=f"(hi) : "l"(v));
    return lo + hi;
}
__device__ __forceinline__ ull pack2(float lo, float hi) {
    ull r;
    asm("mov.b64 %0, {%1, %2};" : "=l"(r) : "f"(lo), "f"(hi));
    return r;
}
__device__ __forceinline__ float tanh_a(float v) {
    float r;
    asm("tanh.approx.f32 %0, %1;" : "=f"(r) : "f"(v));   // MUFU.TANH
    return r;
}
__device__ __forceinline__ void cp_async16(void* smem_dst, const void* gsrc) {
    unsigned saddr = (unsigned)__cvta_generic_to_shared(smem_dst);
    asm volatile("cp.async.ca.shared.global [%0], [%1], 16;" :: "r"(saddr), "l"(gsrc));
}
__device__ __forceinline__ void cp_commit() {
    asm volatile("cp.async.commit_group;" ::: "memory");
}
__device__ __forceinline__ void cp_wait1() {
    asm volatile("cp.async.wait_group 1;" ::: "memory");
}

// ---- templated step loop: NB = batches this warp owns (3 or 4) ----
template <int NB>
__device__ __forceinline__ void lstm_run(
    const int j, const int b0,
    const float* __restrict__ x,
    const ulonglong2* wA, const ulonglong2* wB,   // &wih[ ][j], stride 32 f4
    const ull* biasp,                              // 4 packed (bias,0)
    const ull (&whh2)[4][HH / 2],                  // register weights (scaled)
    float (*h_sw)[4][HH],                          // [2][4][HH] this warp
    float (*xsw)[4][II],                           // [2][4][II]  this warp
    const float* __restrict__ W_fc,
    const float* __restrict__ b_fc,
    float* __restrict__ out)
{
    // cp.async lane map: lanes 0..4*NB-1 -> batch j>>2, 16B chunk j&3
    const int cb = j >> 2, cc = j & 3;
    const float* gsrc = x + (long)(b0 + cb) * TT * II + cc * 4;

    float h[NB], c[NB];
    #pragma unroll
    for (int bb = 0; bb < NB; bb++) { h[bb] = 0.f; c[bb] = 0.f; }

    if (j < 4 * NB) cp_async16(&xsw[0][cb][cc * 4], gsrc);
    cp_commit();

    #pragma unroll 1
    for (int t = 0; t < TT; t++) {
        const int bufx = t & 1;

        // broadcast h (state after step t-1)
        #pragma unroll
        for (int bb = 0; bb < NB; bb++)
            h_sw[bufx][bb][j] = h[bb];

        // prefetch x(t+1) into other buffer (constant group depth)
        const long tn = (t + 1 < TT) ? t + 1 : t;
        if (j < 4 * NB) cp_async16(&xsw[bufx ^ 1][cb][cc * 4], gsrc + tn * II);
        cp_commit();
        cp_wait1();          // current step's x resident
        __syncwarp();        // h + x visible warp-wide

        ull ai[NB], af[NB], ag[NB], ao[NB];
        #pragma unroll
        for (int bb = 0; bb < NB; bb++) {
            ai[bb] = biasp[0]; af[bb] = biasp[1];
            ag[bb] = biasp[2]; ao[bb] = biasp[3];
        }

        // ---- load x pairs (broadcast LDS.128) ----
        ull xp[NB][8];
        #pragma unroll
        for (int bb = 0; bb < NB; bb++) {
            const ulonglong2* xs2 = reinterpret_cast<const ulonglong2*>(&xsw[bufx][bb][0]);
            ulonglong2 q0 = xs2[0], q1 = xs2[1], q2 = xs2[2], q3 = xs2[3];
            xp[bb][0] = q0.x; xp[bb][1] = q0.y; xp[bb][2] = q1.x; xp[bb][3] = q1.y;
            xp[bb][4] = q2.x; xp[bb][5] = q2.y; xp[bb][6] = q3.x; xp[bb][7] = q3.y;
        }

        // ---- input projection: one smem weight read feeds NB batches ----
        #pragma unroll
        for (int i2 = 0; i2 < 8; i2++) {
            ulonglong2 a  = wA[i2 * 32];
            ulonglong2 w2 = wB[i2 * 32];
            #pragma unroll
            for (int bb = 0; bb < NB; bb++) {
                ffma2(ai[bb], a.x,  xp[bb][i2]);
                ffma2(af[bb], a.y,  xp[bb][i2]);
                ffma2(ag[bb], w2.x, xp[bb][i2]);
                ffma2(ao[bb], w2.y, xp[bb][i2]);
            }
        }

        // ---- recurrent matvec: register weights, 4*NB independent chains ----
        #pragma unroll
        for (int kk = 0; kk < 8; kk++) {
            ulonglong2 hq[NB];
            #pragma unroll
            for (int bb = 0; bb < NB; bb++)
                hq[bb] = reinterpret_cast<const ulonglong2*>(&h_sw[bufx][bb][0])[kk];
            #pragma unroll
            for (int bb = 0; bb < NB; bb++) {
                ffma2(ai[bb], whh2[0][2*kk], hq[bb].x); ffma2(ai[bb], whh2[0][2*kk+1], hq[bb].y);
                ffma2(af[bb], whh2[1][2*kk], hq[bb].x); ffma2(af[bb], whh2[1][2*kk+1], hq[bb].y);
                ffma2(ag[bb], whh2[2][2*kk], hq[bb].x); ffma2(ag[bb], whh2[2][2*kk+1], hq[bb].y);
                ffma2(ao[bb], whh2[3][2*kk], hq[bb].x); ffma2(ao[bb], whh2[3][2*kk+1], hq[bb].y);
            }
        }

        // ---- activations (MUFU.TANH; i,f,o pre-scaled by 0.5) ----
        #pragma unroll
        for (int bb = 0; bb < NB; bb++) {
            float gi = fmaf(tanh_a(hadd2(ai[bb])), 0.5f, 0.5f);
            float gf = fmaf(tanh_a(hadd2(af[bb])), 0.5f, 0.5f);
            float gg = tanh_a(hadd2(ag[bb]));
            float go = fmaf(tanh_a(hadd2(ao[bb])), 0.5f, 0.5f);
            c[bb] = fmaf(gf, c[bb], gi * gg);
            h[bb] = go * tanh_a(c[bb]);
        }
    }

    // ---- final FC (O=1): NB warp reductions ----
    float wf = W_fc[j];
    float v[NB];
    #pragma unroll
    for (int bb = 0; bb < NB; bb++) v[bb] = h[bb] * wf;
    #pragma unroll
    for (int off = 16; off; off >>= 1) {
        #pragma unroll
        for (int bb = 0; bb < NB; bb++)
            v[bb] += __shfl_xor_sync(0xffffffffu, v[bb], off);
    }
    if (j == 0) {
        float bf = b_fc[0];
        #pragma unroll
        for (int bb = 0; bb < NB; bb++)
            out[b0 + bb] = v[bb] + bf;
    }
}

__global__ void __launch_bounds__(THREADS, 1)
lstm_bal2_kernel(const float* __restrict__ x,      // [B,T,I]
                 const float* __restrict__ W_ih,   // [4H,I]
                 const float* __restrict__ W_hh,   // [4H,H]
                 const float* __restrict__ b_ih,   // [4H]
                 const float* __restrict__ b_hh,   // [4H]
                 const float* __restrict__ W_fc,   // [1,H]
                 const float* __restrict__ b_fc,   // [1]
                 float* __restrict__ out)          // [B,1]
{
    __shared__ float4 wihA[II / 2][HH];
    __shared__ float4 wihB[II / 2][HH];
    __shared__ float  h_s[WARPS_PER_BLK][2][4][HH];
    __shared__ float  xs[WARPS_PER_BLK][2][4][II];

    const int tid = threadIdx.x;
    const int wid = tid >> 5;
    const int j   = tid & 31;

    // ---- stage W_ih (once per block), gate-scaled ----
    for (int idx = tid; idx < (II / 2) * HH; idx += THREADS) {
        int i2 = idx >> 5, jj = idx & 31;
        wihA[i2][jj] = make_float4(0.5f * W_ih[(0 * HH + jj) * II + 2 * i2],
                                   0.5f * W_ih[(0 * HH + jj) * II + 2 * i2 + 1],
                                   0.5f * W_ih[(1 * HH + jj) * II + 2 * i2],
                                   0.5f * W_ih[(1 * HH + jj) * II + 2 * i2 + 1]);
        wihB[i2][jj] = make_float4(W_ih[(2 * HH + jj) * II + 2 * i2],
                                   W_ih[(2 * HH + jj) * II + 2 * i2 + 1],
                                   0.5f * W_ih[(3 * HH + jj) * II + 2 * i2],
                                   0.5f * W_ih[(3 * HH + jj) * II + 2 * i2 + 1]);
    }
    __syncthreads();

    // ---- W_hh rows (4 gates) as packed pairs, gate-scaled (128 regs) ----
    const float gsc[4] = {0.5f, 0.5f, 1.0f, 0.5f};
    ull whh2[4][HH / 2];
    #pragma unroll
    for (int g = 0; g < 4; g++) {
        const float* wrow = W_hh + (g * HH + j) * HH;
        #pragma unroll
        for (int k2 = 0; k2 < HH / 2; k2++)
            whh2[g][k2] = pack2(gsc[g] * wrow[2 * k2], gsc[g] * wrow[2 * k2 + 1]);
    }

    ull biasp[4];
    #pragma unroll
    for (int g = 0; g < 4; g++)
        biasp[g] = pack2(gsc[g] * (b_ih[g * HH + j] + b_hh[g * HH + j]), 0.0f);

    const ulonglong2* wA = reinterpret_cast<const ulonglong2*>(&wihA[0][j]);
    const ulonglong2* wB = reinterpret_cast<const ulonglong2*>(&wihB[0][j]);

    // ---- SMSP-balanced warp -> batch mapping ----
    // Heavy CTAs (cta < NHEAVY): wid 0-3 -> NB=4, wid 4-7 -> NB=3.
    //   base = cta*28;  wid<4: b0 = base + wid*4;  wid>=4: b0 = base+16+(wid-4)*3
    // Tail CTAs: all NB=3.  base = NHEAVY*28 + (cta-NHEAVY)*24; b0 = base + wid*3
    const int cta = blockIdx.x;
    if (cta < NHEAVY) {
        const int base = cta * 28;
        if (wid < 4) {
            lstm_run<4>(j, base + wid * 4, x, wA, wB, biasp, whh2,
                        h_s[wid], xs[wid], W_fc, b_fc, out);
        } else {
            lstm_run<3>(j, base + 16 + (wid - 4) * 3, x, wA, wB, biasp, whh2,
                        h_s[wid], xs[wid], W_fc, b_fc, out);
        }
    } else {
        const int base = NHEAVY * 28 + (cta - NHEAVY) * 24;
        lstm_run<3>(j, base + wid * 3, x, wA, wB, biasp, whh2,
                    h_s[wid], xs[wid], W_fc, b_fc, out);
    }
}

extern "C" void kernel_launch(void* const* d_in, const int* in_sizes, int n_in,
                              void* d_out, int out_size) {
    (void)in_sizes; (void)n_in; (void)out_size;
    const float* x    = (const float*)d_in[0];
    const float* W_ih = (const float*)d_in[1];
    const float* W_hh = (const float*)d_in[2];
    const float* b_ih = (const float*)d_in[3];
    const float* b_hh = (const float*)d_in[4];
    const float* W_fc = (const float*)d_in[5];
    const float* b_fc = (const float*)d_in[6];
    float* out = (float*)d_out;

    dim3 grid(NCTA);      // 148 CTAs, 1 per SM, single wave
    dim3 block(THREADS);
    lstm_bal2_kernel<<<grid, block>>>(x, W_ih, W_hh, b_ih, b_hh, W_fc, b_fc, out);
}

// round 13
// speedup vs baseline: 1.8319x; 1.0327x over previous
#include <cuda_runtime.h>

// SimpleLSTM: B=4096, T=256, I=16, H=32, O=1 (fp32)
// R13 = R12 (148 CTAs, SMSP-balanced NB=4/3 warp mix, W_hh f32x2 in regs,
// W_ih smem, h broadcast dbl-buffer, cp.async x dbl-buffer, MUFU.TANH) +
// per-step instruction diet:
//   - t unrolled by 2, BUF is a template constant -> smem addrs are imm-offset
//   - bias fused into first x-proj FFMA2 (no accumulator-init MOVs)
//   - no xp staging array

#define BB 4096
#define TT 256
#define II 16
#define HH 32
#define WARPS_PER_BLK 8
#define THREADS (WARPS_PER_BLK * 32)
#define NCTA 148
#define NHEAVY 136   // CTAs with 4+3 split; rest all-3

typedef unsigned long long ull;

__device__ __forceinline__ void ffma2(ull& acc, ull a, ull b) {
    asm("fma.rn.f32x2 %0, %1, %2, %0;" : "+l"(acc) : "l"(a), "l"(b));
}
__device__ __forceinline__ void ffma2_init(ull& acc, ull a, ull b, ull addend) {
    asm("fma.rn.f32x2 %0, %1, %2, %3;" : "=l"(acc) : "l"(a), "l"(b), "l"(addend));
}
__device__ __forceinline__ float hadd2(ull v) {
    float lo, hi;
    asm("mov.b64 {%0, %1}, %2;" : "=f"(lo), "=f"(hi) : "l"(v));
    return lo + hi;
}
__device__ __forceinline__ ull pack2(float lo, float hi) {
    ull r;
    asm("mov.b64 %0, {%1, %2};" : "=l"(r) : "f"(lo), "f"(hi));
    return r;
}
__device__ __forceinline__ float tanh_a(float v) {
    float r;
    asm("tanh.approx.f32 %0, %1;" : "=f"(r) : "f"(v));   // MUFU.TANH
    return r;
}
__device__ __forceinline__ void cp_async16(void* smem_dst, const void* gsrc) {
    unsigned saddr = (unsigned)__cvta_generic_to_shared(smem_dst);
    asm volatile("cp.async.ca.shared.global [%0], [%1], 16;" :: "r"(saddr), "l"(gsrc));
}
__device__ __forceinline__ void cp_commit() {
    asm volatile("cp.async.commit_group;" ::: "memory");
}
__device__ __forceinline__ void cp_wait1() {
    asm volatile("cp.async.wait_group 1;" ::: "memory");
}

// ---- one LSTM step; BUF (0/1) compile-time so smem offsets are immediates ----
template <int NB, int BUF>
__device__ __forceinline__ void lstm_step(
    const int j, float (&h)[NB], float (&c)[NB],
    const ulonglong2* wA, const ulonglong2* wB,
    const ull (&whh2)[4][HH / 2], const ull* biasp,
    float (*h_sw)[4][HH],        // [2][4][HH]
    float (*xsw)[4][II],         // [2][4][II]
    const float* gsrc_next, int cb, int cc)
{
    // broadcast h (state after previous step)
    #pragma unroll
    for (int bb = 0; bb < NB; bb++)
        h_sw[BUF][bb][j] = h[bb];

    // prefetch next x into the other buffer (constant group depth)
    if (j < 4 * NB) cp_async16(&xsw[BUF ^ 1][cb][cc * 4], gsrc_next);
    cp_commit();
    cp_wait1();          // current step's x resident
    __syncwarp();        // h + x visible warp-wide

    ull ai[NB], af[NB], ag[NB], ao[NB];

    // ---- input projection; i2==0 fuses the bias as FFMA2 addend ----
    #pragma unroll
    for (int i2 = 0; i2 < 8; i2++) {
        ulonglong2 a  = wA[i2 * 32];
        ulonglong2 w2 = wB[i2 * 32];
        #pragma unroll
        for (int bb = 0; bb < NB; bb++) {
            ull xp = reinterpret_cast<const ull*>(&xsw[BUF][bb][0])[i2];
            if (i2 == 0) {
                ffma2_init(ai[bb], a.x,  xp, biasp[0]);
                ffma2_init(af[bb], a.y,  xp, biasp[1]);
                ffma2_init(ag[bb], w2.x, xp, biasp[2]);
                ffma2_init(ao[bb], w2.y, xp, biasp[3]);
            } else {
                ffma2(ai[bb], a.x,  xp);
                ffma2(af[bb], a.y,  xp);
                ffma2(ag[bb], w2.x, xp);
                ffma2(ao[bb], w2.y, xp);
            }
        }
    }

    // ---- recurrent matvec: register weights, 4*NB independent chains ----
    #pragma unroll
    for (int kk = 0; kk < 8; kk++) {
        ulonglong2 hq[NB];
        #pragma unroll
        for (int bb = 0; bb < NB; bb++)
            hq[bb] = reinterpret_cast<const ulonglong2*>(&h_sw[BUF][bb][0])[kk];
        #pragma unroll
        for (int bb = 0; bb < NB; bb++) {
            ffma2(ai[bb], whh2[0][2*kk], hq[bb].x); ffma2(ai[bb], whh2[0][2*kk+1], hq[bb].y);
            ffma2(af[bb], whh2[1][2*kk], hq[bb].x); ffma2(af[bb], whh2[1][2*kk+1], hq[bb].y);
            ffma2(ag[bb], whh2[2][2*kk], hq[bb].x); ffma2(ag[bb], whh2[2][2*kk+1], hq[bb].y);
            ffma2(ao[bb], whh2[3][2*kk], hq[bb].x); ffma2(ao[bb], whh2[3][2*kk+1], hq[bb].y);
        }
    }

    // ---- activations (MUFU.TANH; i,f,o pre-scaled by 0.5) ----
    #pragma unroll
    for (int bb = 0; bb < NB; bb++) {
        float gi = fmaf(tanh_a(hadd2(ai[bb])), 0.5f, 0.5f);
        float gf = fmaf(tanh_a(hadd2(af[bb])), 0.5f, 0.5f);
        float gg = tanh_a(hadd2(ag[bb]));
        float go = fmaf(tanh_a(hadd2(ao[bb])), 0.5f, 0.5f);
        c[bb] = fmaf(gf, c[bb], gi * gg);
        h[bb] = go * tanh_a(c[bb]);
    }
}

template <int NB>
__device__ __forceinline__ void lstm_run(
    const int j, const int b0,
    const float* __restrict__ x,
    const ulonglong2* wA, const ulonglong2* wB,
    const ull* biasp,
    const ull (&whh2)[4][HH / 2],
    float (*h_sw)[4][HH],
    float (*xsw)[4][II],
    const float* __restrict__ W_fc,
    const float* __restrict__ b_fc,
    float* __restrict__ out)
{
    const int cb = j >> 2, cc = j & 3;
    const float* gsrc = x + (long)(b0 + cb) * TT * II + cc * 4;

    float h[NB], c[NB];
    #pragma unroll
    for (int bb = 0; bb < NB; bb++) { h[bb] = 0.f; c[bb] = 0.f; }

    // prefetch x(t=0) into buffer 0
    if (j < 4 * NB) cp_async16(&xsw[0][cb][cc * 4], gsrc);
    cp_commit();

    #pragma unroll 1
    for (int t = 0; t < TT; t += 2) {
        // step t   (BUF=0): prefetch x(t+1)  [t+1 <= 255 always]
        lstm_step<NB, 0>(j, h, c, wA, wB, whh2, biasp, h_sw, xsw,
                         gsrc + (long)(t + 1) * II, cb, cc);
        // step t+1 (BUF=1): prefetch x(t+2), clamped at the end
        const int t2 = (t + 2 < TT) ? t + 2 : TT - 1;
        lstm_step<NB, 1>(j, h, c, wA, wB, whh2, biasp, h_sw, xsw,
                         gsrc + (long)t2 * II, cb, cc);
    }

    // ---- final FC (O=1): NB warp reductions ----
    float wf = W_fc[j];
    float v[NB];
    #pragma unroll
    for (int bb = 0; bb < NB; bb++) v[bb] = h[bb] * wf;
    #pragma unroll
    for (int off = 16; off; off >>= 1) {
        #pragma unroll
        for (int bb = 0; bb < NB; bb++)
            v[bb] += __shfl_xor_sync(0xffffffffu, v[bb], off);
    }
    if (j == 0) {
        float bf = b_fc[0];
        #pragma unroll
        for (int bb = 0; bb < NB; bb++)
            out[b0 + bb] = v[bb] + bf;
    }
}

__global__ void __launch_bounds__(THREADS, 1)
lstm_diet_kernel(const float* __restrict__ x,      // [B,T,I]
                 const float* __restrict__ W_ih,   // [4H,I]
                 const float* __restrict__ W_hh,   // [4H,H]
                 const float* __restrict__ b_ih,   // [4H]
                 const float* __restrict__ b_hh,   // [4H]
                 const float* __restrict__ W_fc,   // [1,H]
                 const float* __restrict__ b_fc,   // [1]
                 float* __restrict__ out)          // [B,1]
{
    __shared__ float4 wihA[II / 2][HH];
    __shared__ float4 wihB[II / 2][HH];
    __shared__ float  h_s[WARPS_PER_BLK][2][4][HH];
    __shared__ float  xs[WARPS_PER_BLK][2][4][II];

    const int tid = threadIdx.x;
    const int wid = tid >> 5;
    const int j   = tid & 31;

    // ---- stage W_ih (once per block), gate-scaled ----
    for (int idx = tid; idx < (II / 2) * HH; idx += THREADS) {
        int i2 = idx >> 5, jj = idx & 31;
        wihA[i2][jj] = make_float4(0.5f * W_ih[(0 * HH + jj) * II + 2 * i2],
                                   0.5f * W_ih[(0 * HH + jj) * II + 2 * i2 + 1],
                                   0.5f * W_ih[(1 * HH + jj) * II + 2 * i2],
                                   0.5f * W_ih[(1 * HH + jj) * II + 2 * i2 + 1]);
        wihB[i2][jj] = make_float4(W_ih[(2 * HH + jj) * II + 2 * i2],
                                   W_ih[(2 * HH + jj) * II + 2 * i2 + 1],
                                   0.5f * W_ih[(3 * HH + jj) * II + 2 * i2],
                                   0.5f * W_ih[(3 * HH + jj) * II + 2 * i2 + 1]);
    }
    __syncthreads();

    // ---- W_hh rows (4 gates) as packed pairs, gate-scaled (128 regs) ----
    const float gsc[4] = {0.5f, 0.5f, 1.0f, 0.5f};
    ull whh2[4][HH / 2];
    #pragma unroll
    for (int g = 0; g < 4; g++) {
        const float* wrow = W_hh + (g * HH + j) * HH;
        #pragma unroll
        for (int k2 = 0; k2 < HH / 2; k2++)
            whh2[g][k2] = pack2(gsc[g] * wrow[2 * k2], gsc[g] * wrow[2 * k2 + 1]);
    }

    ull biasp[4];
    #pragma unroll
    for (int g = 0; g < 4; g++)
        biasp[g] = pack2(gsc[g] * (b_ih[g * HH + j] + b_hh[g * HH + j]), 0.0f);

    const ulonglong2* wA = reinterpret_cast<const ulonglong2*>(&wihA[0][j]);
    const ulonglong2* wB = reinterpret_cast<const ulonglong2*>(&wihB[0][j]);

    // ---- SMSP-balanced warp -> batch mapping (R12) ----
    const int cta = blockIdx.x;
    if (cta < NHEAVY) {
        const int base = cta * 28;
        if (wid < 4) {
            lstm_run<4>(j, base + wid * 4, x, wA, wB, biasp, whh2,
                        h_s[wid], xs[wid], W_fc, b_fc, out);
        } else {
            lstm_run<3>(j, base + 16 + (wid - 4) * 3, x, wA, wB, biasp, whh2,
                        h_s[wid], xs[wid], W_fc, b_fc, out);
        }
    } else {
        const int base = NHEAVY * 28 + (cta - NHEAVY) * 24;
        lstm_run<3>(j, base + wid * 3, x, wA, wB, biasp, whh2,
                    h_s[wid], xs[wid], W_fc, b_fc, out);
    }
}

extern "C" void kernel_launch(void* const* d_in, const int* in_sizes, int n_in,
                              void* d_out, int out_size) {
    (void)in_sizes; (void)n_in; (void)out_size;
    const float* x    = (const float*)d_in[0];
    const float* W_ih = (const float*)d_in[1];
    const float* W_hh = (const float*)d_in[2];
    const float* b_ih = (const float*)d_in[3];
    const float* b_hh = (const float*)d_in[4];
    const float* W_fc = (const float*)d_in[5];
    const float* b_fc = (const float*)d_in[6];
    float* out = (float*)d_out;

    dim3 grid(NCTA);      // 148 CTAs, 1 per SM, single wave
    dim3 block(THREADS);
    lstm_diet_kernel<<<grid, block>>>(x, W_ih, W_hh, b_ih, b_hh, W_fc, b_fc, out);
}